// round 8
// baseline (speedup 1.0000x reference)
#include <cuda_runtime.h>
#include <cstdint>

// FilterTransform: cascaded biquads (fixed HP + random coeffs) over time,
// x[4096,16000] and n[4096,16000] -> out [8192,16000].
//
// R8: tile widened 512B -> 800B per row (SEG 32->50, 80 tiles instead of
// 125): fewer per-tile fixed costs (waits/syncs/loop) and longer contiguous
// DRAM bursts per row for better row-buffer locality. Both remaining walls
// are near: HBM 5.63 of ~7 TB/s achievable, and per-warp serial issue.
// Math unchanged (stage 1 exact DF2T w/ immediate coeffs, stage 2 DF-I).

static constexpr int T_LEN   = 16000;
static constexpr int HALF    = 4096;
static constexpr int SEG     = 50;                  // float4 per row per tile (800B)
static constexpr int NTILES  = (T_LEN / 4) / SEG;   // 80
static constexpr int ROWS    = 14;                  // rows per block
static constexpr int XBLOCKS = (HALF + ROWS - 1) / ROWS;  // 293
static constexpr int PAD     = 1;                   // stride 51 float4 = 204 words:
                                                    // 8-lane LDS phases conflict-free

__device__ __forceinline__ void cp_async16(uint32_t saddr, const void* gptr) {
    asm volatile("cp.async.cg.shared.global [%0], [%1], 16;"
                 :: "r"(saddr), "l"(gptr) : "memory");
}
__device__ __forceinline__ void cp_commit() {
    asm volatile("cp.async.commit_group;" ::: "memory");
}
__device__ __forceinline__ void cp_wait2() {
    asm volatile("cp.async.wait_group 2;" ::: "memory");
}

__global__ __launch_bounds__(32)
void biquad_cascade_kernel(const float* __restrict__ x,
                           const float* __restrict__ n,
                           const float* __restrict__ a_x,
                           const float* __restrict__ b_x,
                           const float* __restrict__ a_n,
                           const float* __restrict__ b_n,
                           float* __restrict__ out)
{
    __shared__ float4 tile[3][ROWS][SEG + PAD];

    const int lane = threadIdx.x;
    const bool is_x = (blockIdx.x < XBLOCKS);
    const int bi = is_x ? blockIdx.x : blockIdx.x - XBLOCKS;
    const int rowbase = bi * ROWS;
    const int nrows = (HALF - rowbase) < ROWS ? (HALF - rowbase) : ROWS;

    const float* inbase = is_x ? (x + (size_t)rowbase * T_LEN)
                               : (n + (size_t)rowbase * T_LEN);
    float* outbase = out + (size_t)(is_x ? rowbase : rowbase + HALF) * T_LEN;

    float b0, b1, na0, na1;
    if (is_x) { na0 = -a_x[0]; na1 = -a_x[1]; b0 = b_x[0]; b1 = b_x[1]; }
    else      { na0 = -a_n[0]; na1 = -a_n[1]; b0 = b_n[0]; b1 = b_n[1]; }

    // Stage 1 (HP) DF2T state; stage 2 DF-I histories (u = stage-1 output).
    float m0 = 0.f, m1 = 0.f;
    float u1 = 0.f, u2 = 0.f, v1 = 0.f, v2 = 0.f;

    // 50 float4 per row, covered by 32 lanes in 2 phases (lane, lane+32<50).
    const bool p1 = (lane + 32) < SEG;

    auto issue_tile = [&](int g, int buf) {
        const float* src = inbase + (size_t)g * (SEG * 4);
        for (int i = 0; i < nrows; i++) {
            const float* row = src + (size_t)i * T_LEN;
            uint32_t s0 = (uint32_t)__cvta_generic_to_shared(&tile[buf][i][lane]);
            cp_async16(s0, row + lane * 4);
            if (p1) {
                uint32_t s1 = (uint32_t)__cvta_generic_to_shared(&tile[buf][i][lane + 32]);
                cp_async16(s1, row + (lane + 32) * 4);
            }
        }
    };

    issue_tile(0, 0); cp_commit();
    issue_tile(1, 1); cp_commit();
    issue_tile(2, 2); cp_commit();

    const bool active = (lane < nrows);

    int buf = 0;
    for (int g = 0; g < NTILES; g++) {
        cp_wait2();            // tile g landed (<=2 newer groups pending)
        __syncwarp();

        if (active) {
            float4* myrow = &tile[buf][lane][0];
            float4 nxt = myrow[0];
            #pragma unroll 5
            for (int j = 0; j < SEG; j++) {
                float4 vin = nxt;
                if (j + 1 < SEG) nxt = myrow[j + 1];   // rolling LDS prefetch
                float xs[4] = {vin.x, vin.y, vin.z, vin.w};
                float ys[4];
                #pragma unroll
                for (int k = 0; k < 4; k++) {
                    const float xv = xs[k];
                    // Stage 1: exact DF2T high-pass (immediate coeffs -> FFMA-imm)
                    const float y1 = xv + m0;
                    m0 = fmaf(1.99599f, y1, fmaf(-2.0f, xv, m1));
                    m1 = fmaf(-0.996f, y1, xv);
                    // Stage 2: DF-I with runtime coeffs (well-damped poles)
                    float s = fmaf(b0, u1, y1);
                    s = fmaf(b1, u2, s);
                    s = fmaf(na1, v2, s);
                    const float v = fmaf(na0, v1, s);
                    u2 = u1; u1 = y1;
                    v2 = v1; v1 = v;
                    ys[k] = v;
                }
                myrow[j] = make_float4(ys[0], ys[1], ys[2], ys[3]);
            }
        }
        __syncwarp();

        // Coalesced store: 800B per row in 2 lane phases.
        {
            float* dst = outbase + (size_t)g * (SEG * 4);
            for (int i = 0; i < nrows; i++) {
                float* drow = dst + (size_t)i * T_LEN;
                float4 v0 = tile[buf][i][lane];
                *(float4*)(drow + lane * 4) = v0;
                if (p1) {
                    float4 w = tile[buf][i][lane + 32];
                    *(float4*)(drow + (lane + 32) * 4) = w;
                }
            }
        }
        __syncwarp();          // all lanes done reading buf before refill

        if (g + 3 < NTILES) issue_tile(g + 3, buf);
        cp_commit();           // exactly one group per iteration

        buf = (buf == 2) ? 0 : buf + 1;
    }
}

extern "C" void kernel_launch(void* const* d_in, const int* in_sizes, int n_in,
                              void* d_out, int out_size)
{
    const float* x   = (const float*)d_in[0];
    const float* n   = (const float*)d_in[1];
    const float* a_x = (const float*)d_in[2];
    const float* b_x = (const float*)d_in[3];
    const float* a_n = (const float*)d_in[4];
    const float* b_n = (const float*)d_in[5];
    float* out = (float*)d_out;

    biquad_cascade_kernel<<<2 * XBLOCKS, 32>>>(x, n, a_x, b_x, a_n, b_n, out);
}

// round 9
// speedup vs baseline: 1.0315x; 1.0315x over previous
#include <cuda_runtime.h>
#include <cstdint>

// FilterTransform: cascaded biquads (fixed HP + random coeffs) over time,
// x[4096,16000] and n[4096,16000] -> out [8192,16000].
//
// R9 (from R7 best @177us): per-warp fma rt floor is 1664 cyc/tile; the
// ~1050-cyc gap is memory-instruction issue. Changes:
//  (1) stores via cp.async.bulk S2G (14 bulk ops by lane 0) replacing the
//      14 LDS.128 + 14 STG.128 gather loop; 4-buffer ring gated by
//      cp.async.bulk.wait_group.read so refill never waits on DRAM write.
//  (2) y1 = x + m0 emitted as FFMA-imm (x*1.0 + m0, bit-identical, rt1).

static constexpr int T_LEN   = 16000;
static constexpr int HALF    = 4096;
static constexpr int SEG     = 32;                  // float4 per row per tile (512B)
static constexpr int NTILES  = (T_LEN / 4) / SEG;   // 125
static constexpr int ROWS    = 14;                  // rows per block (1 warp)
static constexpr int XBLOCKS = (HALF + ROWS - 1) / ROWS;  // 293
static constexpr int PAD     = 1;                   // conflict-free LDS; data region
                                                    // of each row stays contiguous 512B
static constexpr int NBUF    = 4;

__device__ __forceinline__ void cp_async16(uint32_t saddr, const void* gptr) {
    asm volatile("cp.async.cg.shared.global [%0], [%1], 16;"
                 :: "r"(saddr), "l"(gptr) : "memory");
}
__device__ __forceinline__ void cp_commit() {
    asm volatile("cp.async.commit_group;" ::: "memory");
}
__device__ __forceinline__ void cp_wait2() {
    asm volatile("cp.async.wait_group 2;" ::: "memory");
}
__device__ __forceinline__ void bulk_s2g(void* gdst, uint32_t ssrc, uint32_t bytes) {
    asm volatile("cp.async.bulk.global.shared::cta.bulk_group [%0], [%1], %2;"
                 :: "l"(gdst), "r"(ssrc), "r"(bytes) : "memory");
}
__device__ __forceinline__ void bulk_commit() {
    asm volatile("cp.async.bulk.commit_group;" ::: "memory");
}
__device__ __forceinline__ void bulk_wait_read1() {
    asm volatile("cp.async.bulk.wait_group.read 1;" ::: "memory");
}
__device__ __forceinline__ void bulk_wait_all() {
    asm volatile("cp.async.bulk.wait_group 0;" ::: "memory");
}
__device__ __forceinline__ void fence_async_shared() {
    asm volatile("fence.proxy.async.shared::cta;" ::: "memory");
}
__device__ __forceinline__ float fma_imm1(float a, float c) {
    // a*1.0 + c as FFMA-imm (rt 1); bit-identical to a + c.
    float d;
    asm("fma.rn.f32 %0, %1, 0f3F800000, %2;" : "=f"(d) : "f"(a), "f"(c));
    return d;
}

__global__ __launch_bounds__(32)
void biquad_cascade_kernel(const float* __restrict__ x,
                           const float* __restrict__ n,
                           const float* __restrict__ a_x,
                           const float* __restrict__ b_x,
                           const float* __restrict__ a_n,
                           const float* __restrict__ b_n,
                           float* __restrict__ out)
{
    __shared__ float4 tile[NBUF][ROWS][SEG + PAD];

    const int lane = threadIdx.x;
    const bool is_x = (blockIdx.x < XBLOCKS);
    const int bi = is_x ? blockIdx.x : blockIdx.x - XBLOCKS;
    const int rowbase = bi * ROWS;
    const int nrows = (HALF - rowbase) < ROWS ? (HALF - rowbase) : ROWS;

    const float* inbase = is_x ? (x + (size_t)rowbase * T_LEN)
                               : (n + (size_t)rowbase * T_LEN);
    float* outbase = out + (size_t)(is_x ? rowbase : rowbase + HALF) * T_LEN;

    float b0, b1, na0, na1;
    if (is_x) { na0 = -a_x[0]; na1 = -a_x[1]; b0 = b_x[0]; b1 = b_x[1]; }
    else      { na0 = -a_n[0]; na1 = -a_n[1]; b0 = b_n[0]; b1 = b_n[1]; }

    // Stage 1 (HP) DF2T state; stage 2 DF-I histories (u = stage-1 output).
    float m0 = 0.f, m1 = 0.f;
    float u1 = 0.f, u2 = 0.f, v1 = 0.f, v2 = 0.f;

    auto issue_tile = [&](int g, int buf) {
        const float* src = inbase + (size_t)g * (SEG * 4) + lane * 4;
        for (int i = 0; i < nrows; i++) {
            uint32_t saddr = (uint32_t)__cvta_generic_to_shared(&tile[buf][i][lane]);
            cp_async16(saddr, src + (size_t)i * T_LEN);
        }
    };

    issue_tile(0, 0); cp_commit();
    issue_tile(1, 1); cp_commit();
    issue_tile(2, 2); cp_commit();

    const bool active = (lane < nrows);
    const bool leader = (lane == 0);

    for (int g = 0; g < NTILES; g++) {
        const int buf = g & (NBUF - 1);

        cp_wait2();            // tile g landed (<=2 newer load groups pending)
        __syncwarp();

        if (active) {
            float4* myrow = &tile[buf][lane][0];
            float4 nxt = myrow[0];
            #pragma unroll 8
            for (int j = 0; j < SEG; j++) {
                float4 vin = nxt;
                if (j + 1 < SEG) nxt = myrow[j + 1];   // rolling LDS prefetch
                float xs[4] = {vin.x, vin.y, vin.z, vin.w};
                float ys[4];
                #pragma unroll
                for (int k = 0; k < 4; k++) {
                    const float xv = xs[k];
                    // Stage 1: exact DF2T high-pass (all three as FFMA-imm rt1)
                    const float y1 = fma_imm1(xv, m0);
                    m0 = fmaf(1.99599f, y1, fmaf(-2.0f, xv, m1));
                    m1 = fmaf(-0.996f, y1, xv);
                    // Stage 2: DF-I with runtime coeffs (well-damped poles)
                    float s = fmaf(b0, u1, y1);
                    s = fmaf(b1, u2, s);
                    s = fmaf(na1, v2, s);
                    const float v = fmaf(na0, v1, s);
                    u2 = u1; u1 = y1;
                    v2 = v1; v1 = v;
                    ys[k] = v;
                }
                myrow[j] = make_float4(ys[0], ys[1], ys[2], ys[3]);
            }
        }
        __syncwarp();

        // Bulk-async store: 512B contiguous per row, read by the async proxy.
        if (leader) {
            fence_async_shared();      // order STS (generic proxy) before bulk reads
            float* dst = outbase + (size_t)g * (SEG * 4);
            for (int i = 0; i < nrows; i++) {
                uint32_t ssrc = (uint32_t)__cvta_generic_to_shared(&tile[buf][i][0]);
                bulk_s2g(dst + (size_t)i * T_LEN, ssrc, SEG * 16);
            }
            bulk_commit();
            bulk_wait_read1();         // reads of group g-1 done -> its buf reusable
        }
        __syncwarp();

        // Refill buf (g+3)%4 = (g-1)%4, whose bulk group (g-1) has drained reads.
        if (g + 3 < NTILES) issue_tile(g + 3, (g + 3) & (NBUF - 1));
        cp_commit();                   // exactly one load group per iteration

    }

    if (leader) bulk_wait_all();       // all bulk stores complete before exit
}

extern "C" void kernel_launch(void* const* d_in, const int* in_sizes, int n_in,
                              void* d_out, int out_size)
{
    const float* x   = (const float*)d_in[0];
    const float* n   = (const float*)d_in[1];
    const float* a_x = (const float*)d_in[2];
    const float* b_x = (const float*)d_in[3];
    const float* a_n = (const float*)d_in[4];
    const float* b_n = (const float*)d_in[5];
    float* out = (float*)d_out;

    biquad_cascade_kernel<<<2 * XBLOCKS, 32>>>(x, n, a_x, b_x, a_n, b_n, out);
}